// round 9
// baseline (speedup 1.0000x reference)
#include <cuda_runtime.h>

#define NN 50000
#define EE 800000
#define HH 4
#define HD 64               // H*D
#define SLOT 64             // padded bucket size per node (Poisson(16): P(deg>64) ~ 1e-20)
#define QKV_NB 782          // ceil(50000/64)
#define SCAT_B 1600
#define ATTN_B 6250         // NN/8 warps-per-block

// ---------------- scratch (device globals; zero-initialized at load) ----------------
__device__ float  g_Q[NN * HD];
__device__ float  g_K[NN * HD];
__device__ float  g_V[NN * HD];
__device__ int    g_cnt[NN];         // invariant: zero at kernel_launch entry (attn owner-warp re-zeroes)
__device__ int    g_es[NN * SLOT];   // padded edge buckets: src indices
__device__ float4 g_w[NN * SLOT];    // per-edge-slot distance weights, one float per head

// ---------------- packed f32x2 helpers ----------------
__device__ __forceinline__ unsigned long long pk2(float x, float y) {
    unsigned long long r; asm("mov.b64 %0, {%1, %2};" : "=l"(r) : "f"(x), "f"(y)); return r;
}
__device__ __forceinline__ float2 upk2(unsigned long long v) {
    float2 f; asm("mov.b64 {%0, %1}, %2;" : "=f"(f.x), "=f"(f.y) : "l"(v)); return f;
}
__device__ __forceinline__ unsigned long long ffma2(unsigned long long a, unsigned long long b, unsigned long long c) {
    unsigned long long d;
    asm("fma.rn.f32x2 %0, %1, %2, %3;" : "=l"(d) : "l"(a), "l"(b), "l"(c));
    return d;
}

// ---------------- QKV tile: 64 nodes/block, packed-f32x2 FMA ----------------
__device__ __forceinline__ void qkv_tile(
    int n0, int t,
    const float* __restrict__ h,
    const float* __restrict__ Wq, const float* __restrict__ bq,
    const float* __restrict__ Wk, const float* __restrict__ bk,
    const float* __restrict__ Wv, const float* __restrict__ bv)
{
    __shared__ float4 hs[64][16];   // 64 nodes x 64 floats (16KB)
    __shared__ float4 Ws[64][16];   // 64x64 W (16KB)
    __shared__ float4 bs[16];

    for (int i = t; i < 64 * 16; i += 256) {
        int n = i >> 4, k4 = i & 15;
        int gn = n0 + n; if (gn >= NN) gn = NN - 1;   // clamp (tail) — writes guarded
        hs[n][k4] = ((const float4*)h)[gn * 16 + k4];
    }

    int c4 = t & 15;
    int ng = t >> 4;

    for (int m = 0; m < 3; m++) {
        const float* Wm = (m == 0) ? Wq : ((m == 1) ? Wk : Wv);
        const float* bm = (m == 0) ? bq : ((m == 1) ? bk : bv);
        float*       Om = (m == 0) ? g_Q : ((m == 1) ? g_K : g_V);

        __syncthreads();
        for (int i = t; i < 64 * 16; i += 256) Ws[i >> 4][i & 15] = ((const float4*)Wm)[i];
        if (t < 16) bs[t] = ((const float4*)bm)[t];
        __syncthreads();

        float4 bb = bs[c4];
        unsigned long long axy[4], azw[4];
        #pragma unroll
        for (int q = 0; q < 4; q++) { axy[q] = pk2(bb.x, bb.y); azw[q] = pk2(bb.z, bb.w); }

        #pragma unroll
        for (int kq = 0; kq < 16; kq++) {
            float4 w0 = Ws[kq * 4 + 0][c4];
            float4 w1 = Ws[kq * 4 + 1][c4];
            float4 w2 = Ws[kq * 4 + 2][c4];
            float4 w3 = Ws[kq * 4 + 3][c4];
            unsigned long long w0a = pk2(w0.x, w0.y), w0b = pk2(w0.z, w0.w);
            unsigned long long w1a = pk2(w1.x, w1.y), w1b = pk2(w1.z, w1.w);
            unsigned long long w2a = pk2(w2.x, w2.y), w2b = pk2(w2.z, w2.w);
            unsigned long long w3a = pk2(w3.x, w3.y), w3b = pk2(w3.z, w3.w);
            #pragma unroll
            for (int q = 0; q < 4; q++) {
                float4 hv = hs[ng * 4 + q][kq];
                unsigned long long h0 = pk2(hv.x, hv.x), h1 = pk2(hv.y, hv.y);
                unsigned long long h2 = pk2(hv.z, hv.z), h3 = pk2(hv.w, hv.w);
                axy[q] = ffma2(h0, w0a, axy[q]); azw[q] = ffma2(h0, w0b, azw[q]);
                axy[q] = ffma2(h1, w1a, axy[q]); azw[q] = ffma2(h1, w1b, azw[q]);
                axy[q] = ffma2(h2, w2a, axy[q]); azw[q] = ffma2(h2, w2b, azw[q]);
                axy[q] = ffma2(h3, w3a, axy[q]); azw[q] = ffma2(h3, w3b, azw[q]);
            }
        }

        int gn = n0 + ng * 4;
        #pragma unroll
        for (int q = 0; q < 4; q++) {
            if (gn + q < NN) {
                float2 lo = upk2(axy[q]), hi = upk2(azw[q]);
                ((float4*)Om)[(gn + q) * 16 + c4] = make_float4(lo.x, lo.y, hi.x, hi.y);
            }
        }
    }
}

// ---------------- K1: QKV GEMM + bucket scatter with distance-weight precompute ----------------
__global__ void __launch_bounds__(256) k1_qkv_scatter(
    const float* __restrict__ h,
    const float* __restrict__ Wq, const float* __restrict__ bq,
    const float* __restrict__ Wk, const float* __restrict__ bk,
    const float* __restrict__ Wv, const float* __restrict__ bv,
    const int* __restrict__ src, const int* __restrict__ dst,
    const float* __restrict__ s_l)
{
    int b = blockIdx.x, t = threadIdx.x;
    if (b < QKV_NB) {
        qkv_tile(b * 64, t, h, Wq, bq, Wk, bk, Wv, bv);
    } else {
        int bb = b - QKV_NB;
        for (int e = bb * 256 + t; e < EE; e += SCAT_B * 256) {
            int d   = dst[e];
            int s   = src[e];
            int pos = atomicAdd(&g_cnt[d], 1);
            if (pos < SLOT) {
                int slot = d * SLOT + pos;
                g_es[slot] = s;
                // precompute per-head distance weight w = exp(-dij^2)
                // (bit-identical fp expression to the previous attn-side computation)
                const float4* sp = (const float4*)(s_l + s * 12);
                const float4* dp = (const float4*)(s_l + d * 12);
                float4 sa = sp[0], sb = sp[1], sc4 = sp[2];
                float4 da = dp[0], db = dp[1], dc4 = dp[2];
                float w4x, w4y, w4z, w4w;
                {   // head 0: comps (sa.x,sa.y,sa.z)
                    float dx = sa.x - da.x, dy = sa.y - da.y, dz = sa.z - da.z;
                    float dij = fmaf(dx, dx, fmaf(dy, dy, dz * dz));
                    w4x = __expf(-dij * dij);
                }
                {   // head 1: comps (sa.w,sb.x,sb.y)
                    float dx = sa.w - da.w, dy = sb.x - db.x, dz = sb.y - db.y;
                    float dij = fmaf(dx, dx, fmaf(dy, dy, dz * dz));
                    w4y = __expf(-dij * dij);
                }
                {   // head 2: comps (sb.z,sb.w,sc.x)
                    float dx = sb.z - db.z, dy = sb.w - db.w, dz = sc4.x - dc4.x;
                    float dij = fmaf(dx, dx, fmaf(dy, dy, dz * dz));
                    w4z = __expf(-dij * dij);
                }
                {   // head 3: comps (sc.y,sc.z,sc.w)
                    float dx = sc4.y - dc4.y, dy = sc4.z - dc4.z, dz = sc4.w - dc4.w;
                    float dij = fmaf(dx, dx, fmaf(dy, dy, dz * dz));
                    w4w = __expf(-dij * dij);
                }
                g_w[slot] = make_float4(w4x, w4y, w4z, w4w);
            }
        }
    }
}

// ---------------- K2: warp-per-node attn, 16 lanes/edge, smem indices, precomputed w ----------
// Lane l: eh = l>>4 (edge of pair), hh = (l>>2)&3 (head), dq = (l&3)*4 (dim quad).
#define ELOAD(sv, ee, kk, vv, ww)                                                \
    kk = *(const float4*)(g_K + (sv) * HD + off);                                \
    vv = *(const float4*)(g_V + (sv) * HD + off);                                \
    ww = ((const float*)(g_w + wbase + (ee)))[hh];

#define ECOMP(kk, vv, ww, act)                                                   \
    {                                                                            \
        float pd = fmaf(q.x, kk.x, fmaf(q.y, kk.y, fmaf(q.z, kk.z, q.w * kk.w))); \
        pd += __shfl_xor_sync(FULL, pd, 1);                                      \
        pd += __shfl_xor_sync(FULL, pd, 2);                                      \
        float arg = fminf(fmaxf(pd * 0.25f, -5.f), 5.f);                         \
        float sc  = __expf(arg);                                                 \
        float scz  = (act) ? sc : 0.f;                                           \
        float news = scz * (ww);                                                 \
        a.x = fmaf(vv.x, news, a.x); a.y = fmaf(vv.y, news, a.y);                \
        a.z = fmaf(vv.z, news, a.z); a.w = fmaf(vv.w, news, a.w);                \
        z  += scz;                                                               \
    }

__global__ void __launch_bounds__(256) attn_kernel(float* __restrict__ out)
{
    const unsigned FULL = 0xffffffffu;
    __shared__ int sidx[8][64];
    int wslot = threadIdx.x >> 5;
    int n = blockIdx.x * 8 + wslot;
    if (n >= NN) return;
    int lane = threadIdx.x & 31;
    int eh   = lane >> 4;            // 0/1: which edge of the pair
    int hh   = (lane >> 2) & 3;      // head
    int dq   = (lane & 3) * 4;       // dim quad
    int off  = hh * 16 + dq;

    float4 q = *(const float4*)(g_Q + n * HD + off);

    // owner warp reads degree then restores zero-invariant (only this warp touches g_cnt[n])
    int cnt = 0;
    if (lane == 0) { cnt = g_cnt[n]; g_cnt[n] = 0; }
    cnt = __shfl_sync(FULL, cnt, 0);
    cnt = min(cnt, SLOT);
    const int wbase = n * SLOT;

    // stage all edge indices in shared memory (one coalesced LDG per 32)
    sidx[wslot][lane]      = (lane < cnt)      ? g_es[wbase + lane]      : 0;
    sidx[wslot][32 + lane] = (32 + lane < cnt) ? g_es[wbase + 32 + lane] : 0;
    __syncwarp();

    float4 a = make_float4(0.f, 0.f, 0.f, 0.f);
    float  z = 0.f;

    for (int j = 0; j < cnt; j += 4) {
        int e0 = j + eh, e1 = j + 2 + eh;          // max e = 63, always in-bounds
        int s0 = sidx[wslot][e0];
        int s1 = sidx[wslot][e1];
        bool a0 = e0 < cnt, a1 = e1 < cnt;
        float4 k0, v0, k1, v1; float w0, w1;
        ELOAD(s0, e0, k0, v0, w0)
        ELOAD(s1, e1, k1, v1, w1)
        ECOMP(k0, v0, w0, a0)
        ECOMP(k1, v1, w1, a1)
    }

    // combine the two edge-halves
    a.x += __shfl_xor_sync(FULL, a.x, 16);
    a.y += __shfl_xor_sync(FULL, a.y, 16);
    a.z += __shfl_xor_sync(FULL, a.z, 16);
    a.w += __shfl_xor_sync(FULL, a.w, 16);
    z   += __shfl_xor_sync(FULL, z, 16);

    float inv = (z > 0.f) ? (1.f / z) : 1.f;   // degree-0 nodes: a = 0, write 0
    if (eh == 0)
        *(float4*)(out + n * HD + off) = make_float4(a.x * inv, a.y * inv, a.z * inv, a.w * inv);
}

// ---------------- launch ----------------
extern "C" void kernel_launch(void* const* d_in, const int* in_sizes, int n_in,
                              void* d_out, int out_size)
{
    const float* h   = (const float*)d_in[0];
    const float* s_l = (const float*)d_in[1];
    const float* Wq  = (const float*)d_in[2];
    const float* bq  = (const float*)d_in[3];
    const float* Wk  = (const float*)d_in[4];
    const float* bk  = (const float*)d_in[5];
    const float* Wv  = (const float*)d_in[6];
    const float* bv  = (const float*)d_in[7];
    const int*   src = (const int*)d_in[8];
    const int*   dst = (const int*)d_in[9];
    float*       out = (float*)d_out;

    k1_qkv_scatter<<<QKV_NB + SCAT_B, 256>>>(h, Wq, bq, Wk, bk, Wv, bv, src, dst, s_l); // launch 0
    attn_kernel<<<ATTN_B, 256>>>(out);                                                  // launch 1
}

// round 12
// speedup vs baseline: 1.0400x; 1.0400x over previous
#include <cuda_runtime.h>

#define NN 50000
#define EE 800000
#define HH 4
#define HD 64               // H*D
#define SLOT 64             // padded bucket size per node (Poisson(16): P(deg>64) ~ 1e-20)
#define QKV_NB 782          // ceil(50000/64)
#define SCAT_B 1600
#define ATTN_B 6250         // NN/8 warps-per-block

// ---------------- scratch (device globals; zero-initialized at load) ----------------
__device__ float g_Q[NN * HD];
__device__ float g_K[NN * HD];
__device__ float g_V[NN * HD];
__device__ int   g_cnt[NN];          // invariant: zero at kernel_launch entry (attn owner-warp re-zeroes)
__device__ int   g_es[NN * SLOT];    // padded edge buckets: src indices

// ---------------- packed f32x2 helpers ----------------
__device__ __forceinline__ unsigned long long pk2(float x, float y) {
    unsigned long long r; asm("mov.b64 %0, {%1, %2};" : "=l"(r) : "f"(x), "f"(y)); return r;
}
__device__ __forceinline__ float2 upk2(unsigned long long v) {
    float2 f; asm("mov.b64 {%0, %1}, %2;" : "=f"(f.x), "=f"(f.y) : "l"(v)); return f;
}
__device__ __forceinline__ unsigned long long ffma2(unsigned long long a, unsigned long long b, unsigned long long c) {
    unsigned long long d;
    asm("fma.rn.f32x2 %0, %1, %2, %3;" : "=l"(d) : "l"(a), "l"(b), "l"(c));
    return d;
}
__device__ __forceinline__ float ex2(float x) {   // raw exp2; __expf(x) == ex2(x*log2e)
    float r; asm("ex2.approx.f32 %0, %1;" : "=f"(r) : "f"(x)); return r;
}

// ---------------- QKV tile: 64 nodes/block, packed-f32x2 FMA ----------------
__device__ __forceinline__ void qkv_tile(
    int n0, int t,
    const float* __restrict__ h,
    const float* __restrict__ Wq, const float* __restrict__ bq,
    const float* __restrict__ Wk, const float* __restrict__ bk,
    const float* __restrict__ Wv, const float* __restrict__ bv)
{
    __shared__ float4 hs[64][16];   // 64 nodes x 64 floats (16KB)
    __shared__ float4 Ws[64][16];   // 64x64 W (16KB)
    __shared__ float4 bs[16];

    for (int i = t; i < 64 * 16; i += 256) {
        int n = i >> 4, k4 = i & 15;
        int gn = n0 + n; if (gn >= NN) gn = NN - 1;   // clamp (tail) — writes guarded
        hs[n][k4] = ((const float4*)h)[gn * 16 + k4];
    }

    int c4 = t & 15;
    int ng = t >> 4;

    for (int m = 0; m < 3; m++) {
        const float* Wm = (m == 0) ? Wq : ((m == 1) ? Wk : Wv);
        const float* bm = (m == 0) ? bq : ((m == 1) ? bk : bv);
        float*       Om = (m == 0) ? g_Q : ((m == 1) ? g_K : g_V);

        __syncthreads();
        for (int i = t; i < 64 * 16; i += 256) Ws[i >> 4][i & 15] = ((const float4*)Wm)[i];
        if (t < 16) bs[t] = ((const float4*)bm)[t];
        __syncthreads();

        float4 bb = bs[c4];
        unsigned long long axy[4], azw[4];
        #pragma unroll
        for (int q = 0; q < 4; q++) { axy[q] = pk2(bb.x, bb.y); azw[q] = pk2(bb.z, bb.w); }

        #pragma unroll
        for (int kq = 0; kq < 16; kq++) {
            float4 w0 = Ws[kq * 4 + 0][c4];
            float4 w1 = Ws[kq * 4 + 1][c4];
            float4 w2 = Ws[kq * 4 + 2][c4];
            float4 w3 = Ws[kq * 4 + 3][c4];
            unsigned long long w0a = pk2(w0.x, w0.y), w0b = pk2(w0.z, w0.w);
            unsigned long long w1a = pk2(w1.x, w1.y), w1b = pk2(w1.z, w1.w);
            unsigned long long w2a = pk2(w2.x, w2.y), w2b = pk2(w2.z, w2.w);
            unsigned long long w3a = pk2(w3.x, w3.y), w3b = pk2(w3.z, w3.w);
            #pragma unroll
            for (int q = 0; q < 4; q++) {
                float4 hv = hs[ng * 4 + q][kq];
                unsigned long long h0 = pk2(hv.x, hv.x), h1 = pk2(hv.y, hv.y);
                unsigned long long h2 = pk2(hv.z, hv.z), h3 = pk2(hv.w, hv.w);
                axy[q] = ffma2(h0, w0a, axy[q]); azw[q] = ffma2(h0, w0b, azw[q]);
                axy[q] = ffma2(h1, w1a, axy[q]); azw[q] = ffma2(h1, w1b, azw[q]);
                axy[q] = ffma2(h2, w2a, axy[q]); azw[q] = ffma2(h2, w2b, azw[q]);
                axy[q] = ffma2(h3, w3a, axy[q]); azw[q] = ffma2(h3, w3b, azw[q]);
            }
        }

        int gn = n0 + ng * 4;
        #pragma unroll
        for (int q = 0; q < 4; q++) {
            if (gn + q < NN) {
                float2 lo = upk2(axy[q]), hi = upk2(azw[q]);
                ((float4*)Om)[(gn + q) * 16 + c4] = make_float4(lo.x, lo.y, hi.x, hi.y);
            }
        }
    }
}

// ---------------- K1: QKV GEMM + direct bucket scatter (R8 form — no w precompute) ----------------
__global__ void __launch_bounds__(256) k1_qkv_scatter(
    const float* __restrict__ h,
    const float* __restrict__ Wq, const float* __restrict__ bq,
    const float* __restrict__ Wk, const float* __restrict__ bk,
    const float* __restrict__ Wv, const float* __restrict__ bv,
    const int* __restrict__ src, const int* __restrict__ dst)
{
    int b = blockIdx.x, t = threadIdx.x;
    if (b < QKV_NB) {
        qkv_tile(b * 64, t, h, Wq, bq, Wk, bk, Wv, bv);
    } else {
        int bb = b - QKV_NB;
        for (int e = bb * 256 + t; e < EE; e += SCAT_B * 256) {
            int d   = dst[e];
            int pos = atomicAdd(&g_cnt[d], 1);
            if (pos < SLOT) g_es[d * SLOT + pos] = src[e];
        }
    }
}

// ---------------- K2: warp-per-node attn, 16 lanes/edge, 8-deep pipeline, in-loop s_l ----------
// Lane l: eh = l>>4 (edge of pair), hh = (l>>2)&3 (head), dq = (l&3)*4 (dim quad).
// Q is pre-scaled by 0.25*log2e so the score is ex2(clamp(pd, +-5*log2e)).
#define C_QSCL 0.3606737602222409f    // 0.25 * log2(e)
#define C_CLMP 7.2134752044448170f    // 5 * log2(e)
#define C_L2E  1.4426950408889634f    // log2(e)

#define ELOAD(sv, kk, vv, sl)                                                    \
    kk = *(const float4*)(g_K + (sv) * HD + off);                                \
    vv = *(const float4*)(g_V + (sv) * HD + off);                                \
    sl = (hl < 12) ? __ldg(s_l + (sv) * 12 + hl) : 0.f;

#define ECOMP(kk, vv, sl, act)                                                   \
    {                                                                            \
        float dx = __shfl_sync(FULL, sl, slb + 0, 16) - sx;                      \
        float dy = __shfl_sync(FULL, sl, slb + 1, 16) - sy;                      \
        float dz = __shfl_sync(FULL, sl, slb + 2, 16) - sz;                      \
        float pd = fmaf(q.x, kk.x, fmaf(q.y, kk.y, fmaf(q.z, kk.z, q.w * kk.w))); \
        pd += __shfl_xor_sync(FULL, pd, 1);                                      \
        pd += __shfl_xor_sync(FULL, pd, 2);                                      \
        float sc  = ex2(fminf(fmaxf(pd, -C_CLMP), C_CLMP));                      \
        float dij = fmaf(dx, dx, fmaf(dy, dy, dz * dz));                         \
        float w   = ex2(-dij * dij * C_L2E);                                     \
        float scz  = (act) ? sc : 0.f;                                           \
        float news = scz * w;                                                    \
        a.x = fmaf(vv.x, news, a.x); a.y = fmaf(vv.y, news, a.y);                \
        a.z = fmaf(vv.z, news, a.z); a.w = fmaf(vv.w, news, a.w);                \
        z  += scz;                                                               \
    }

__global__ void __launch_bounds__(256) attn_kernel(
    const float* __restrict__ s_l, float* __restrict__ out)
{
    const unsigned FULL = 0xffffffffu;
    __shared__ int sidx[8][64];
    int wslot = threadIdx.x >> 5;
    int n = blockIdx.x * 8 + wslot;
    if (n >= NN) return;
    int lane = threadIdx.x & 31;
    int eh   = lane >> 4;            // 0/1: which edge of the pair
    int hl   = lane & 15;            // lane within 16-lane half
    int hh   = (lane >> 2) & 3;      // head
    int dq   = (lane & 3) * 4;       // dim quad
    int off  = hh * 16 + dq;

    float4 q = *(const float4*)(g_Q + n * HD + off);
    q.x *= C_QSCL; q.y *= C_QSCL; q.z *= C_QSCL; q.w *= C_QSCL;

    int slb = hh * 3;
    float sx = __ldg(s_l + n * 12 + slb + 0);
    float sy = __ldg(s_l + n * 12 + slb + 1);
    float sz = __ldg(s_l + n * 12 + slb + 2);

    // owner warp reads degree then restores zero-invariant (only this warp touches g_cnt[n])
    int cnt = 0;
    if (lane == 0) { cnt = g_cnt[n]; g_cnt[n] = 0; }
    cnt = __shfl_sync(FULL, cnt, 0);
    cnt = min(cnt, SLOT);
    const int base = n * SLOT;

    // stage all edge indices in shared memory (one coalesced LDG per 32)
    sidx[wslot][lane]      = (lane < cnt)      ? g_es[base + lane]      : 0;
    sidx[wslot][32 + lane] = (32 + lane < cnt) ? g_es[base + 32 + lane] : 0;
    __syncwarp();

    float4 a = make_float4(0.f, 0.f, 0.f, 0.f);
    float  z = 0.f;

    for (int j = 0; j < cnt; j += 8) {
        int e0 = j + eh, e1 = j + 2 + eh, e2 = j + 4 + eh, e3 = j + 6 + eh;  // max 63, in-bounds
        int s0 = sidx[wslot][e0];
        int s1 = sidx[wslot][e1];
        int s2 = sidx[wslot][e2];
        int s3 = sidx[wslot][e3];
        bool a0 = e0 < cnt, a1 = e1 < cnt, a2 = e2 < cnt, a3 = e3 < cnt;
        float4 k0, v0, k1, v1, k2, v2, k3, v3;
        float  sl0, sl1, sl2, sl3;
        ELOAD(s0, k0, v0, sl0)
        ELOAD(s1, k1, v1, sl1)
        ELOAD(s2, k2, v2, sl2)
        ELOAD(s3, k3, v3, sl3)
        ECOMP(k0, v0, sl0, a0)
        ECOMP(k1, v1, sl1, a1)
        ECOMP(k2, v2, sl2, a2)
        ECOMP(k3, v3, sl3, a3)
    }

    // combine the two edge-halves
    a.x += __shfl_xor_sync(FULL, a.x, 16);
    a.y += __shfl_xor_sync(FULL, a.y, 16);
    a.z += __shfl_xor_sync(FULL, a.z, 16);
    a.w += __shfl_xor_sync(FULL, a.w, 16);
    z   += __shfl_xor_sync(FULL, z, 16);

    float inv = (z > 0.f) ? (1.f / z) : 1.f;   // degree-0 nodes: a = 0, write 0
    if (eh == 0)
        *(float4*)(out + n * HD + off) = make_float4(a.x * inv, a.y * inv, a.z * inv, a.w * inv);
}

// ---------------- launch ----------------
extern "C" void kernel_launch(void* const* d_in, const int* in_sizes, int n_in,
                              void* d_out, int out_size)
{
    const float* h   = (const float*)d_in[0];
    const float* s_l = (const float*)d_in[1];
    const float* Wq  = (const float*)d_in[2];
    const float* bq  = (const float*)d_in[3];
    const float* Wk  = (const float*)d_in[4];
    const float* bk  = (const float*)d_in[5];
    const float* Wv  = (const float*)d_in[6];
    const float* bv  = (const float*)d_in[7];
    const int*   src = (const int*)d_in[8];
    const int*   dst = (const int*)d_in[9];
    float*       out = (float*)d_out;

    k1_qkv_scatter<<<QKV_NB + SCAT_B, 256>>>(h, Wq, bq, Wk, bk, Wv, bv, src, dst); // launch 0
    attn_kernel<<<ATTN_B, 256>>>(s_l, out);                                        // launch 1
}

// round 13
// speedup vs baseline: 1.0936x; 1.0515x over previous
#include <cuda_runtime.h>

#define NN 50000
#define EE 800000
#define HH 4
#define HD 64               // H*D
#define SLOT 64             // padded bucket size per node (Poisson(16): P(deg>64) ~ 1e-20)
#define QKV_NB 782          // ceil(50000/64)
#define SCAT_B 600
#define ATTN_B 6250         // NN/8 warps-per-block

// ---------------- scratch (device globals; zero-initialized at load) ----------------
__device__ float g_Q[NN * HD];
__device__ float g_K[NN * HD];
__device__ float g_V[NN * HD];
__device__ int   g_cnt[NN];          // invariant: zero at kernel_launch entry (attn owner-warp re-zeroes)
__device__ int   g_es[NN * SLOT];    // padded edge buckets: src indices

// ---------------- packed f32x2 helpers ----------------
__device__ __forceinline__ unsigned long long pk2(float x, float y) {
    unsigned long long r; asm("mov.b64 %0, {%1, %2};" : "=l"(r) : "f"(x), "f"(y)); return r;
}
__device__ __forceinline__ float2 upk2(unsigned long long v) {
    float2 f; asm("mov.b64 {%0, %1}, %2;" : "=f"(f.x), "=f"(f.y) : "l"(v)); return f;
}
__device__ __forceinline__ unsigned long long ffma2(unsigned long long a, unsigned long long b, unsigned long long c) {
    unsigned long long d;
    asm("fma.rn.f32x2 %0, %1, %2, %3;" : "=l"(d) : "l"(a), "l"(b), "l"(c));
    return d;
}
__device__ __forceinline__ float ex2(float x) {   // raw exp2; __expf(x) == ex2(x*log2e)
    float r; asm("ex2.approx.f32 %0, %1;" : "=f"(r) : "f"(x)); return r;
}

// ---------------- QKV tile: 64 nodes/block, packed-f32x2 FMA ----------------
__device__ __forceinline__ void qkv_tile(
    int n0, int t,
    const float* __restrict__ h,
    const float* __restrict__ Wq, const float* __restrict__ bq,
    const float* __restrict__ Wk, const float* __restrict__ bk,
    const float* __restrict__ Wv, const float* __restrict__ bv)
{
    __shared__ float4 hs[64][16];   // 64 nodes x 64 floats (16KB)
    __shared__ float4 Ws[64][16];   // 64x64 W (16KB)
    __shared__ float4 bs[16];

    for (int i = t; i < 64 * 16; i += 256) {
        int n = i >> 4, k4 = i & 15;
        int gn = n0 + n; if (gn >= NN) gn = NN - 1;   // clamp (tail) — writes guarded
        hs[n][k4] = ((const float4*)h)[gn * 16 + k4];
    }

    int c4 = t & 15;
    int ng = t >> 4;

    for (int m = 0; m < 3; m++) {
        const float* Wm = (m == 0) ? Wq : ((m == 1) ? Wk : Wv);
        const float* bm = (m == 0) ? bq : ((m == 1) ? bk : bv);
        float*       Om = (m == 0) ? g_Q : ((m == 1) ? g_K : g_V);

        __syncthreads();
        for (int i = t; i < 64 * 16; i += 256) Ws[i >> 4][i & 15] = ((const float4*)Wm)[i];
        if (t < 16) bs[t] = ((const float4*)bm)[t];
        __syncthreads();

        float4 bb = bs[c4];
        unsigned long long axy[4], azw[4];
        #pragma unroll
        for (int q = 0; q < 4; q++) { axy[q] = pk2(bb.x, bb.y); azw[q] = pk2(bb.z, bb.w); }

        #pragma unroll
        for (int kq = 0; kq < 16; kq++) {
            float4 w0 = Ws[kq * 4 + 0][c4];
            float4 w1 = Ws[kq * 4 + 1][c4];
            float4 w2 = Ws[kq * 4 + 2][c4];
            float4 w3 = Ws[kq * 4 + 3][c4];
            unsigned long long w0a = pk2(w0.x, w0.y), w0b = pk2(w0.z, w0.w);
            unsigned long long w1a = pk2(w1.x, w1.y), w1b = pk2(w1.z, w1.w);
            unsigned long long w2a = pk2(w2.x, w2.y), w2b = pk2(w2.z, w2.w);
            unsigned long long w3a = pk2(w3.x, w3.y), w3b = pk2(w3.z, w3.w);
            #pragma unroll
            for (int q = 0; q < 4; q++) {
                float4 hv = hs[ng * 4 + q][kq];
                unsigned long long h0 = pk2(hv.x, hv.x), h1 = pk2(hv.y, hv.y);
                unsigned long long h2 = pk2(hv.z, hv.z), h3 = pk2(hv.w, hv.w);
                axy[q] = ffma2(h0, w0a, axy[q]); azw[q] = ffma2(h0, w0b, azw[q]);
                axy[q] = ffma2(h1, w1a, axy[q]); azw[q] = ffma2(h1, w1b, azw[q]);
                axy[q] = ffma2(h2, w2a, axy[q]); azw[q] = ffma2(h2, w2b, azw[q]);
                axy[q] = ffma2(h3, w3a, axy[q]); azw[q] = ffma2(h3, w3b, azw[q]);
            }
        }

        int gn = n0 + ng * 4;
        #pragma unroll
        for (int q = 0; q < 4; q++) {
            if (gn + q < NN) {
                float2 lo = upk2(axy[q]), hi = upk2(azw[q]);
                ((float4*)Om)[(gn + q) * 16 + c4] = make_float4(lo.x, lo.y, hi.x, hi.y);
            }
        }
    }
}

// ---------------- K1: QKV GEMM + direct bucket scatter ----------------
__global__ void __launch_bounds__(256) k1_qkv_scatter(
    const float* __restrict__ h,
    const float* __restrict__ Wq, const float* __restrict__ bq,
    const float* __restrict__ Wk, const float* __restrict__ bk,
    const float* __restrict__ Wv, const float* __restrict__ bv,
    const int* __restrict__ src, const int* __restrict__ dst)
{
    int b = blockIdx.x, t = threadIdx.x;
    if (b < QKV_NB) {
        qkv_tile(b * 64, t, h, Wq, bq, Wk, bk, Wv, bv);
    } else {
        int bb = b - QKV_NB;
        for (int e = bb * 256 + t; e < EE; e += SCAT_B * 256) {
            int d   = dst[e];
            int pos = atomicAdd(&g_cnt[d], 1);
            if (pos < SLOT) g_es[d * SLOT + pos] = src[e];
        }
    }
}

// ---------------- K2: warp-per-node attn, 16 lanes/edge, 4-deep pipeline, in-loop s_l ----------
// Lane l: eh = l>>4 (edge of pair), hh = (l>>2)&3 (head), dq = (l&3)*4 (dim quad).
// Q is pre-scaled by 0.25*log2e so the score is ex2(clamp(pd, +-5*log2e)).
#define C_QSCL 0.3606737602222409f    // 0.25 * log2(e)
#define C_CLMP 7.2134752044448170f    // 5 * log2(e)
#define C_L2E  1.4426950408889634f    // log2(e)

#define ELOAD(sv, kk, vv, sl)                                                    \
    kk = *(const float4*)(g_K + (sv) * HD + off);                                \
    vv = *(const float4*)(g_V + (sv) * HD + off);                                \
    sl = (hl < 12) ? __ldg(s_l + (sv) * 12 + hl) : 0.f;

#define ECOMP(kk, vv, sl, act)                                                   \
    {                                                                            \
        float dx = __shfl_sync(FULL, sl, slb + 0, 16) - sx;                      \
        float dy = __shfl_sync(FULL, sl, slb + 1, 16) - sy;                      \
        float dz = __shfl_sync(FULL, sl, slb + 2, 16) - sz;                      \
        float pd = fmaf(q.x, kk.x, fmaf(q.y, kk.y, fmaf(q.z, kk.z, q.w * kk.w))); \
        pd += __shfl_xor_sync(FULL, pd, 1);                                      \
        pd += __shfl_xor_sync(FULL, pd, 2);                                      \
        float sc  = ex2(fminf(fmaxf(pd, -C_CLMP), C_CLMP));                      \
        float dij = fmaf(dx, dx, fmaf(dy, dy, dz * dz));                         \
        float w   = ex2(-dij * dij * C_L2E);                                     \
        float scz  = (act) ? sc : 0.f;                                           \
        float news = scz * w;                                                    \
        a.x = fmaf(vv.x, news, a.x); a.y = fmaf(vv.y, news, a.y);                \
        a.z = fmaf(vv.z, news, a.z); a.w = fmaf(vv.w, news, a.w);                \
        z  += scz;                                                               \
    }

__global__ void __launch_bounds__(256) attn_kernel(
    const float* __restrict__ s_l, float* __restrict__ out)
{
    const unsigned FULL = 0xffffffffu;
    __shared__ int sidx[8][64];
    int wslot = threadIdx.x >> 5;
    int n = blockIdx.x * 8 + wslot;
    if (n >= NN) return;
    int lane = threadIdx.x & 31;
    int eh   = lane >> 4;            // 0/1: which edge of the pair
    int hl   = lane & 15;            // lane within 16-lane half
    int hh   = (lane >> 2) & 3;      // head
    int dq   = (lane & 3) * 4;       // dim quad
    int off  = hh * 16 + dq;

    float4 q = *(const float4*)(g_Q + n * HD + off);
    q.x *= C_QSCL; q.y *= C_QSCL; q.z *= C_QSCL; q.w *= C_QSCL;

    int slb = hh * 3;
    float sx = __ldg(s_l + n * 12 + slb + 0);
    float sy = __ldg(s_l + n * 12 + slb + 1);
    float sz = __ldg(s_l + n * 12 + slb + 2);

    // owner warp reads degree then restores zero-invariant (only this warp touches g_cnt[n])
    int cnt = 0;
    if (lane == 0) { cnt = g_cnt[n]; g_cnt[n] = 0; }
    cnt = __shfl_sync(FULL, cnt, 0);
    cnt = min(cnt, SLOT);
    const int base = n * SLOT;

    // stage all edge indices in shared memory (one coalesced LDG per 32)
    sidx[wslot][lane]      = (lane < cnt)      ? g_es[base + lane]      : 0;
    sidx[wslot][32 + lane] = (32 + lane < cnt) ? g_es[base + 32 + lane] : 0;
    __syncwarp();

    float4 a = make_float4(0.f, 0.f, 0.f, 0.f);
    float  z = 0.f;

    for (int j = 0; j < cnt; j += 4) {
        int e0 = j + eh, e1 = j + 2 + eh;          // max 63, always in-bounds
        int s0 = sidx[wslot][e0];
        int s1 = sidx[wslot][e1];
        bool a0 = e0 < cnt, a1 = e1 < cnt;
        float4 k0, v0, k1, v1;
        float  sl0, sl1;
        ELOAD(s0, k0, v0, sl0)
        ELOAD(s1, k1, v1, sl1)
        ECOMP(k0, v0, sl0, a0)
        ECOMP(k1, v1, sl1, a1)
    }

    // combine the two edge-halves
    a.x += __shfl_xor_sync(FULL, a.x, 16);
    a.y += __shfl_xor_sync(FULL, a.y, 16);
    a.z += __shfl_xor_sync(FULL, a.z, 16);
    a.w += __shfl_xor_sync(FULL, a.w, 16);
    z   += __shfl_xor_sync(FULL, z, 16);

    float inv = (z > 0.f) ? (1.f / z) : 1.f;   // degree-0 nodes: a = 0, write 0
    if (eh == 0)
        *(float4*)(out + n * HD + off) = make_float4(a.x * inv, a.y * inv, a.z * inv, a.w * inv);
}

// ---------------- launch ----------------
extern "C" void kernel_launch(void* const* d_in, const int* in_sizes, int n_in,
                              void* d_out, int out_size)
{
    const float* h   = (const float*)d_in[0];
    const float* s_l = (const float*)d_in[1];
    const float* Wq  = (const float*)d_in[2];
    const float* bq  = (const float*)d_in[3];
    const float* Wk  = (const float*)d_in[4];
    const float* bk  = (const float*)d_in[5];
    const float* Wv  = (const float*)d_in[6];
    const float* bv  = (const float*)d_in[7];
    const int*   src = (const int*)d_in[8];
    const int*   dst = (const int*)d_in[9];
    float*       out = (float*)d_out;

    k1_qkv_scatter<<<QKV_NB + SCAT_B, 256>>>(h, Wq, bq, Wk, bk, Wv, bv, src, dst); // launch 0
    attn_kernel<<<ATTN_B, 256>>>(s_l, out);                                        // launch 1
}